// round 16
// baseline (speedup 1.0000x reference)
#include <cuda_runtime.h>
#include <cuda_bf16.h>
#include <cstdint>

// GDLoss: elementwise Gaussian KL loss over [N,5] xywhr boxes. 176MB traffic.
// R16 = R12 (per-warp autonomous cp.async rings, compile-time slots, slim
// math; champion: kernel 28.4us, DRAM 75.0%) with 64-box warp tiles:
//   - 2 boxes/thread -> per-box ISSUE/wait/syncwarp/loop overhead halves
//   - 10x LDS.64 (stride-10-word, conflict-free) replaces 20x LDS.32
//   - STG.64 output
//   - 2-stage ring, 40KB smem/block -> 5 blocks/SM, 40 warps
// R12 residual: issue 61.5% / ALU 25.6% = bookkeeping; this halves it per box.

#define TAU_F   1.0f
#define EPS_F   1e-6f
#define BLK     256
#define NW      (BLK / 32)           // 8 warps
#define STAGES  2
#define WTILE   64                   // boxes per warp-tile (2 per lane)
#define WTF     (WTILE * 5)          // 320 floats per tensor per warp-tile
#define WTV4    (WTF / 4)            // 80 float4 per tensor per warp-tile
#define GRID_P  760                  // 5 blocks/SM * 152 SMs

__device__ __forceinline__ void cp_async16(unsigned smem_dst, const void* gmem_src) {
    asm volatile("cp.async.cg.shared.global [%0], [%1], 16;\n"
                 :: "r"(smem_dst), "l"(gmem_src));
}
__device__ __forceinline__ void cp_async4(unsigned smem_dst, const void* gmem_src) {
    asm volatile("cp.async.ca.shared.global [%0], [%1], 4;\n"
                 :: "r"(smem_dst), "l"(gmem_src));
}
__device__ __forceinline__ void cp_commit() {
    asm volatile("cp.async.commit_group;\n" ::: "memory");
}
template <int N>
__device__ __forceinline__ void cp_wait() {
    asm volatile("cp.async.wait_group %0;\n" :: "n"(N) : "memory");
}

__device__ __forceinline__ float rcp_fast(float x) {
    float r; asm("rcp.approx.f32 %0, %1;" : "=f"(r) : "f"(x)); return r;
}
__device__ __forceinline__ float sqrt_fast(float x) {
    float r; asm("sqrt.approx.f32 %0, %1;" : "=f"(r) : "f"(x)); return r;
}

// loss for one box pair (algebraically reduced):
//   det_t = tww*thh/16, det_p = pww*phh/16     (rotation-invariant, no trig)
//   t1num = ths(dx^2+dy^2) - thd(c2t(dx^2-dy^2) + 2 s2t dx dy)
//   n2num = 2(ths*phs - thd*phd*cos(2rt-2rp))
//   dis   = (t1num+n2num)*16/(tww*thh) + log((tww*thh)/(pww*phh)) - 2
__device__ __forceinline__ float gd_loss_one(
    float px, float py, float pw, float ph, float prr,
    float tx, float ty, float tw, float th, float trr)
{
    pw = fminf(fmaxf(pw, 1e-7f), 1e7f);
    ph = fminf(fmaxf(ph, 1e-7f), 1e7f);
    tw = fminf(fmaxf(tw, 1e-7f), 1e7f);
    th = fminf(fmaxf(th, 1e-7f), 1e7f);

    const float pww = pw * pw, phh = ph * ph;
    const float tww = tw * tw, thh = th * th;

    const float phs = 0.125f * (pww + phh);
    const float phd = 0.125f * (pww - phh);
    const float ths = 0.125f * (tww + thh);
    const float thd = 0.125f * (tww - thh);

    float s2t, c2t;
    __sincosf(2.0f * trr, &s2t, &c2t);
    const float cdd = __cosf(2.0f * (trr - prr));   // cos(2rt - 2rp)

    const float dx = px - tx;
    const float dy = py - ty;
    const float dx2 = dx * dx, dy2 = dy * dy;
    const float sum2 = dx2 + dy2, dif2 = dx2 - dy2;
    const float dxy = dx * dy;

    const float rot   = fmaf(c2t, dif2, 2.0f * s2t * dxy);
    const float t1num = fmaf(ths, sum2, -thd * rot);
    const float n2num = 2.0f * fmaf(-thd * phd, cdd, ths * phs);

    const float dtt = tww * thh;                    // 16*det_t
    const float dpp = pww * phh;                    // 16*det_p
    const float invdt16 = 16.0f * rcp_fast(dtt);
    const float logterm = __logf(dtt * rcp_fast(dpp));

    const float dis = fmaf(t1num + n2num, invdt16, logterm - 2.0f);
    const float kl = fmaxf(dis, EPS_F);
    return 1.0f - rcp_fast(TAU_F + sqrt_fast(kl));
}

__global__ void __launch_bounds__(BLK) gd_loss_kernel(
    const float* __restrict__ pred,
    const float* __restrict__ target,
    float* __restrict__ out,
    int n)
{
    // [warp][stage][tensor 0=pred 1=target][320 floats]
    __shared__ float sbuf[NW][STAGES][2][WTF];

    const int lane = threadIdx.x & 31;
    const int wid  = threadIdx.x >> 5;

    const int numTiles = (n + WTILE - 1) / WTILE;   // 62500 for N=4M
    const int wstride  = gridDim.x * NW;
    const int wstart   = blockIdx.x * NW + wid;
    if (wstart >= numTiles) return;

    const unsigned sbase = (unsigned)__cvta_generic_to_shared(&sbuf[wid][0][0][0]);
    const unsigned lane16 = (unsigned)lane * 16u;

    // Issue-side carried state.
    int iTile = wstart;
    const float4* ipp4 = (const float4*)pred   + (size_t)wstart * WTV4;
    const float4* ipt4 = (const float4*)target + (size_t)wstart * WTV4;
    const int ptrStep = wstride * WTV4;

    // ISSUE(SLOT): cp.async tile `iTile` into compile-time SLOT; commits; advances.
    // 80 float4 per tensor: lane -> i, i+32; lanes<16 -> i+64.
#define ISSUE(SLOT) do {                                                      \
    if (iTile < numTiles) {                                                   \
        const int inb = n - iTile * WTILE;                                    \
        const unsigned dsp = sbase + (unsigned)((SLOT) * (2 * WTF * 4));      \
        const unsigned dst_ = dsp + (unsigned)(WTF * 4);                      \
        if (inb >= WTILE) {                                                   \
            cp_async16(dsp + lane16,          ipp4 + lane);                   \
            cp_async16(dst_ + lane16,          ipt4 + lane);                  \
            cp_async16(dsp + lane16 + 512u,   ipp4 + lane + 32);              \
            cp_async16(dst_ + lane16 + 512u,   ipt4 + lane + 32);             \
            if (lane < 16) {                                                  \
                cp_async16(dsp + lane16 + 1024u, ipp4 + lane + 64);           \
                cp_async16(dst_ + lane16 + 1024u, ipt4 + lane + 64);          \
            }                                                                 \
        } else {                                                              \
            const float* pb = (const float*)ipp4;                             \
            const float* tb = (const float*)ipt4;                             \
            const int nf = inb * 5;                                           \
            for (int i = lane; i < nf; i += 32) {                             \
                cp_async4(dsp + (unsigned)i * 4u, pb + i);                    \
                cp_async4(dst_ + (unsigned)i * 4u, tb + i);                   \
            }                                                                 \
        }                                                                     \
    }                                                                         \
    cp_commit();                                                              \
    iTile += wstride; ipp4 += ptrStep; ipt4 += ptrStep;                       \
} while (0)

    // Prologue: two warp-tiles in flight (slots 0, 1).
    ISSUE(0);
    ISSUE(1);

    // Compute-side carried state.
    int tile = wstart;
    const int b0 = 2 * lane;                       // first box of this lane
    float* outp = out + (size_t)wstart * WTILE + b0;
    const int outStep = wstride * WTILE;

    // STEP(SLOT): wait this tile's group, compute 2 boxes, refill same slot.
#define STEP(SLOT) do {                                                       \
    cp_wait<1>();                                                             \
    __syncwarp();                                                             \
    {                                                                         \
        const int nb = n - tile * WTILE;                                      \
        const float2* p2 = (const float2*)(&sbuf[wid][SLOT][0][0]) + lane * 5;\
        const float2* t2 = (const float2*)(&sbuf[wid][SLOT][1][0]) + lane * 5;\
        if (b0 + 1 < nb) {                                                    \
            const float2 pA = p2[0], pB = p2[1], pC = p2[2],                  \
                         pD = p2[3], pE = p2[4];                              \
            const float2 tA = t2[0], tB = t2[1], tC = t2[2],                  \
                         tD = t2[3], tE = t2[4];                              \
            float2 res;                                                       \
            res.x = gd_loss_one(pA.x, pA.y, pB.x, pB.y, pC.x,                 \
                                tA.x, tA.y, tB.x, tB.y, tC.x);                \
            res.y = gd_loss_one(pC.y, pD.x, pD.y, pE.x, pE.y,                 \
                                tC.y, tD.x, tD.y, tE.x, tE.y);                \
            *(float2*)outp = res;                                             \
        } else if (b0 < nb) {                                                 \
            const float2 pA = p2[0], pB = p2[1];                              \
            const float  pE = ((const float*)p2)[4];                          \
            const float2 tA = t2[0], tB = t2[1];                              \
            const float  tE = ((const float*)t2)[4];                          \
            *outp = gd_loss_one(pA.x, pA.y, pB.x, pB.y, pE,                   \
                                tA.x, tA.y, tB.x, tB.y, tE);                  \
        }                                                                     \
    }                                                                         \
    __syncwarp();                                                             \
    ISSUE(SLOT);                                                              \
    tile += wstride; outp += outStep;                                         \
} while (0)

    for (;;) {
        STEP(0); if (tile >= numTiles) break;
        STEP(1); if (tile >= numTiles) break;
    }

#undef STEP
#undef ISSUE
}

extern "C" void kernel_launch(void* const* d_in, const int* in_sizes, int n_in,
                              void* d_out, int out_size)
{
    const float* pred   = (const float*)d_in[0];
    const float* target = (const float*)d_in[1];
    // d_in[2] (weight) is unused by the reference computation (LOSS_WEIGHT=1).
    float* out = (float*)d_out;

    const int n = out_size;                        // N boxes; output [N,1] floats
    const int numTiles = (n + WTILE - 1) / WTILE;  // 62500 for N=4M
    int grid = GRID_P;
    const int maxGrid = (numTiles + NW - 1) / NW;
    if (grid > maxGrid) grid = maxGrid;
    if (grid < 1) grid = 1;
    gd_loss_kernel<<<grid, BLK>>>(pred, target, out, n);
}

// round 17
// speedup vs baseline: 1.0727x; 1.0727x over previous
#include <cuda_runtime.h>
#include <cuda_bf16.h>
#include <cstdint>

// GDLoss: elementwise Gaussian KL loss over [N,5] xywhr boxes. 176MB traffic.
// R17 = R12 (champion: per-warp autonomous cp.async rings, 32-box tiles,
// compile-time slots, slim math; kernel 28.4us, DRAM 75.0%) with lookahead
// deepened: 4-stage ring + wait_group<2> -> THREE tiles in flight per warp
// during every compute phase (R12 had two; R16 showed lookahead depth is
// what matters). smem 41KB -> 5 blocks/SM; R14 proved fewer warps with more
// per-warp MLP sustains DRAM.

#define TAU_F   1.0f
#define EPS_F   1e-6f
#define BLK     256
#define NW      (BLK / 32)           // 8 warps
#define STAGES  4
#define WTILE   32                   // boxes per warp-tile
#define WTF     (WTILE * 5)          // 160 floats per tensor per warp-tile
#define GRID_P  760                  // 5 blocks/SM * 152 SMs

__device__ __forceinline__ void cp_async16(unsigned smem_dst, const void* gmem_src) {
    asm volatile("cp.async.cg.shared.global [%0], [%1], 16;\n"
                 :: "r"(smem_dst), "l"(gmem_src));
}
__device__ __forceinline__ void cp_async4(unsigned smem_dst, const void* gmem_src) {
    asm volatile("cp.async.ca.shared.global [%0], [%1], 4;\n"
                 :: "r"(smem_dst), "l"(gmem_src));
}
__device__ __forceinline__ void cp_commit() {
    asm volatile("cp.async.commit_group;\n" ::: "memory");
}
template <int N>
__device__ __forceinline__ void cp_wait() {
    asm volatile("cp.async.wait_group %0;\n" :: "n"(N) : "memory");
}

__device__ __forceinline__ float rcp_fast(float x) {
    float r; asm("rcp.approx.f32 %0, %1;" : "=f"(r) : "f"(x)); return r;
}
__device__ __forceinline__ float sqrt_fast(float x) {
    float r; asm("sqrt.approx.f32 %0, %1;" : "=f"(r) : "f"(x)); return r;
}

// loss for one box pair (algebraically reduced):
//   det_t = tww*thh/16, det_p = pww*phh/16     (rotation-invariant, no trig)
//   t1num = ths(dx^2+dy^2) - thd(c2t(dx^2-dy^2) + 2 s2t dx dy)
//   n2num = 2(ths*phs - thd*phd*cos(2rt-2rp))
//   dis   = (t1num+n2num)*16/(tww*thh) + log((tww*thh)/(pww*phh)) - 2
__device__ __forceinline__ float gd_loss_one(
    float px, float py, float pw, float ph, float prr,
    float tx, float ty, float tw, float th, float trr)
{
    pw = fminf(fmaxf(pw, 1e-7f), 1e7f);
    ph = fminf(fmaxf(ph, 1e-7f), 1e7f);
    tw = fminf(fmaxf(tw, 1e-7f), 1e7f);
    th = fminf(fmaxf(th, 1e-7f), 1e7f);

    const float pww = pw * pw, phh = ph * ph;
    const float tww = tw * tw, thh = th * th;

    const float phs = 0.125f * (pww + phh);
    const float phd = 0.125f * (pww - phh);
    const float ths = 0.125f * (tww + thh);
    const float thd = 0.125f * (tww - thh);

    float s2t, c2t;
    __sincosf(2.0f * trr, &s2t, &c2t);
    const float cdd = __cosf(2.0f * (trr - prr));   // cos(2rt - 2rp)

    const float dx = px - tx;
    const float dy = py - ty;
    const float dx2 = dx * dx, dy2 = dy * dy;
    const float sum2 = dx2 + dy2, dif2 = dx2 - dy2;
    const float dxy = dx * dy;

    const float rot   = fmaf(c2t, dif2, 2.0f * s2t * dxy);
    const float t1num = fmaf(ths, sum2, -thd * rot);
    const float n2num = 2.0f * fmaf(-thd * phd, cdd, ths * phs);

    const float dtt = tww * thh;                    // 16*det_t
    const float dpp = pww * phh;                    // 16*det_p
    const float invdt16 = 16.0f * rcp_fast(dtt);
    const float logterm = __logf(dtt * rcp_fast(dpp));

    const float dis = fmaf(t1num + n2num, invdt16, logterm - 2.0f);
    const float kl = fmaxf(dis, EPS_F);
    return 1.0f - rcp_fast(TAU_F + sqrt_fast(kl));
}

__global__ void __launch_bounds__(BLK) gd_loss_kernel(
    const float* __restrict__ pred,
    const float* __restrict__ target,
    float* __restrict__ out,
    int n)
{
    // [warp][stage][tensor 0=pred 1=target][160 floats]
    __shared__ float sbuf[NW][STAGES][2][WTF];

    const int lane = threadIdx.x & 31;
    const int wid  = threadIdx.x >> 5;
    const int b5   = lane * 5;

    const int numTiles = (n + WTILE - 1) / WTILE;
    const int wstride  = gridDim.x * NW;
    const int wstart   = blockIdx.x * NW + wid;
    if (wstart >= numTiles) return;

    // Per-warp smem base (shared-space address), one cvta total.
    const unsigned sbase = (unsigned)__cvta_generic_to_shared(&sbuf[wid][0][0][0]);
    const unsigned lane16 = (unsigned)lane * 16u;

    // Issue-side carried state: tile index + gmem pointers, strength-reduced.
    int iTile = wstart;
    const float4* ipp4 = (const float4*)pred   + (size_t)wstart * (WTF / 4);
    const float4* ipt4 = (const float4*)target + (size_t)wstart * (WTF / 4);
    const int ptrStep = wstride * (WTF / 4);     // float4s per issue step

    // ISSUE(SLOT): cp.async this warp's tile `iTile` into compile-time SLOT.
    // Always commits one group; advances carried state.
#define ISSUE(SLOT) do {                                                      \
    if (iTile < numTiles) {                                                   \
        const int inb = n - iTile * WTILE;                                    \
        const unsigned dsp = sbase + (unsigned)((SLOT) * (2 * WTF * 4));      \
        const unsigned dst_ = dsp + (unsigned)(WTF * 4);                      \
        if (inb >= WTILE) {                                                   \
            cp_async16(dsp + lane16, ipp4 + lane);                            \
            cp_async16(dst_ + lane16, ipt4 + lane);                           \
            if (lane < 8) {                                                   \
                cp_async16(dsp + lane16 + 512u, ipp4 + lane + 32);            \
                cp_async16(dst_ + lane16 + 512u, ipt4 + lane + 32);           \
            }                                                                 \
        } else {                                                              \
            const float* pb = (const float*)ipp4;                             \
            const float* tb = (const float*)ipt4;                             \
            const int nf = inb * 5;                                           \
            for (int i = lane; i < nf; i += 32) {                             \
                cp_async4(dsp + (unsigned)i * 4u, pb + i);                    \
                cp_async4(dst_ + (unsigned)i * 4u, tb + i);                   \
            }                                                                 \
        }                                                                     \
    }                                                                         \
    cp_commit();                                                              \
    iTile += wstride; ipp4 += ptrStep; ipt4 += ptrStep;                       \
} while (0)

    // Prologue: THREE warp-tiles in flight (slots 0, 1, 2).
    ISSUE(0);
    ISSUE(1);
    ISSUE(2);

    // Compute-side carried state.
    int tile = wstart;
    float* outp = out + (size_t)wstart * WTILE + lane;
    const int outStep = wstride * WTILE;

    // STEP(SLOT, ISLOT): wait (2 groups still pending), refill ISLOT,
    // compute + store SLOT.
#define STEP(SLOT, ISLOT) do {                                                \
    cp_wait<2>();                                                             \
    __syncwarp();                                                             \
    ISSUE(ISLOT);                                                             \
    {                                                                         \
        const int nb = n - tile * WTILE;                                      \
        const float* spb = sbuf[wid][SLOT][0];                                \
        const float* stb = sbuf[wid][SLOT][1];                                \
        if (lane < nb) {                                                      \
            const float loss = gd_loss_one(                                   \
                spb[b5 + 0], spb[b5 + 1], spb[b5 + 2], spb[b5 + 3], spb[b5 + 4], \
                stb[b5 + 0], stb[b5 + 1], stb[b5 + 2], stb[b5 + 3], stb[b5 + 4]); \
            __stcs(outp, loss);                                               \
        }                                                                     \
    }                                                                         \
    tile += wstride; outp += outStep;                                         \
} while (0)

    for (;;) {
        STEP(0, 3); if (tile >= numTiles) break;
        STEP(1, 0); if (tile >= numTiles) break;
        STEP(2, 1); if (tile >= numTiles) break;
        STEP(3, 2); if (tile >= numTiles) break;
    }

#undef STEP
#undef ISSUE
}

extern "C" void kernel_launch(void* const* d_in, const int* in_sizes, int n_in,
                              void* d_out, int out_size)
{
    const float* pred   = (const float*)d_in[0];
    const float* target = (const float*)d_in[1];
    // d_in[2] (weight) is unused by the reference computation (LOSS_WEIGHT=1).
    float* out = (float*)d_out;

    const int n = out_size;                        // N boxes; output [N,1] floats
    const int numTiles = (n + WTILE - 1) / WTILE;  // 125000 for N=4M
    int grid = GRID_P;
    const int maxGrid = (numTiles + NW - 1) / NW;
    if (grid > maxGrid) grid = maxGrid;
    if (grid < 1) grid = 1;
    gd_loss_kernel<<<grid, BLK>>>(pred, target, out, n);
}